// round 10
// baseline (speedup 1.0000x reference)
#include <cuda_runtime.h>
#include <cuda_bf16.h>
#include <cstdint>

// FourierBlock B=32 L=2048 H=8 E=64 M=64 — mma.sync (HMMA) bf16 split version.
//  K1: X[bh][k=128(re|im)][i=64] = FB[k][l] @ q[b,:,h,:]   (K=2048)
//  K2: O2[bh][k][o] complex mix with W (fp32 FFMA), emits bf16 hi/lo [k][o]
//  K3: y[bh][o][l]  = O2^T[o][k] @ IB^T[k][l]              (K=128)
// All big GEMMs: 3-term bf16 hi/lo split (hh + hl + lh), fp32 accumulate.

#define NL 2048

__device__ unsigned short g_FBh[128 * NL], g_FBl[128 * NL];   // [k][l]
__device__ unsigned short g_IBh[NL * 128], g_IBl[NL * 128];   // [l][k]
__device__ float g_WtR[8 * 64 * 64 * 64], g_WtI[8 * 64 * 64 * 64]; // [h][m][i][o]
__device__ float g_XF[256 * 128 * 64];                        // [bh][k][i]
__device__ unsigned g_O2h[256 * 128 * 32], g_O2l[256 * 128 * 32]; // [bh][k][o/2] bf16x2

// ---------------- helpers ----------------
__device__ __forceinline__ unsigned s2u(const void* p) {
    unsigned a;
    asm("{ .reg .u64 t; cvta.to.shared.u64 t, %1; cvt.u32.u64 %0, t; }" : "=r"(a) : "l"(p));
    return a;
}
__device__ __forceinline__ void ldm_x4(unsigned addr, unsigned* r) {
    asm volatile("ldmatrix.sync.aligned.m8n8.x4.shared.b16 {%0,%1,%2,%3}, [%4];"
        : "=r"(r[0]), "=r"(r[1]), "=r"(r[2]), "=r"(r[3]) : "r"(addr));
}
__device__ __forceinline__ void ldm_x4t(unsigned addr, unsigned* r) {
    asm volatile("ldmatrix.sync.aligned.m8n8.x4.trans.shared.b16 {%0,%1,%2,%3}, [%4];"
        : "=r"(r[0]), "=r"(r[1]), "=r"(r[2]), "=r"(r[3]) : "r"(addr));
}
__device__ __forceinline__ void ldm_x2(unsigned addr, unsigned* r) {
    asm volatile("ldmatrix.sync.aligned.m8n8.x2.shared.b16 {%0,%1}, [%2];"
        : "=r"(r[0]), "=r"(r[1]) : "r"(addr));
}
__device__ __forceinline__ void ldm_x2t(unsigned addr, unsigned* r) {
    asm volatile("ldmatrix.sync.aligned.m8n8.x2.trans.shared.b16 {%0,%1}, [%2];"
        : "=r"(r[0]), "=r"(r[1]) : "r"(addr));
}
__device__ __forceinline__ void mma_bf16(float* c, const unsigned* a, const unsigned* b) {
    asm volatile("mma.sync.aligned.m16n8k16.row.col.f32.bf16.bf16.f32 "
        "{%0,%1,%2,%3}, {%4,%5,%6,%7}, {%8,%9}, {%0,%1,%2,%3};"
        : "+f"(c[0]), "+f"(c[1]), "+f"(c[2]), "+f"(c[3])
        : "r"(a[0]), "r"(a[1]), "r"(a[2]), "r"(a[3]), "r"(b[0]), "r"(b[1]));
}
// packed split: (x0,x1) fp32 -> bf16x2 hi word + bf16x2 lo word (6 instr / 2 values)
__device__ __forceinline__ void hl2(float x0, float x1, unsigned& hw, unsigned& lw) {
    unsigned h;
    asm("cvt.rn.bf16x2.f32 %0, %1, %2;" : "=r"(h) : "f"(x1), "f"(x0)); // hi=x1, lo=x0
    float h0 = __uint_as_float(h << 16);
    float h1 = __uint_as_float(h & 0xffff0000u);
    float l0 = x0 - h0, l1 = x1 - h1;
    asm("cvt.rn.bf16x2.f32 %0, %1, %2;" : "=r"(lw) : "f"(l1), "f"(l0));
    hw = h;
}

// ---------------- K0a: forward basis (bf16 hi/lo) ----------------
__global__ __launch_bounds__(256) void k_basisF(const int* __restrict__ index) {
    int t = blockIdx.x * 256 + threadIdx.x;    // 0..262143
    int k = t >> 11, l = t & 2047, kf = k & 63;
    int p = (index[kf] * l) & 2047;
    float s, c;
    sincospif((float)p * (1.0f / 1024.0f), &s, &c);
    float v = (k < 64) ? c : -s;
    __nv_bfloat16 hb = __float2bfloat16_rn(v);
    g_FBh[t] = __bfloat16_as_ushort(hb);
    g_FBl[t] = __bfloat16_as_ushort(__float2bfloat16_rn(v - __bfloat162float(hb)));
}
// ---------------- K0c: inverse basis (bf16 hi/lo) ----------------
__global__ __launch_bounds__(256) void k_basisI() {
    int t = blockIdx.x * 256 + threadIdx.x;
    int l = t >> 7, k = t & 127, kf = k & 63;
    int p = (kf * l) & 2047;
    float s, c;
    sincospif((float)p * (1.0f / 1024.0f), &s, &c);
    float amp = (kf == 0) ? ((k < 64) ? (1.0f / (float)NL) : 0.0f) : (2.0f / (float)NL);
    float v = (k < 64) ? amp * c : -amp * s;
    __nv_bfloat16 hb = __float2bfloat16_rn(v);
    g_IBh[t] = __bfloat16_as_ushort(hb);
    g_IBl[t] = __bfloat16_as_ushort(__float2bfloat16_rn(v - __bfloat162float(hb)));
}

// ---------------- K0b: transpose W [h][i][o][m] -> [h][m][i][o] ----------------
__global__ __launch_bounds__(256) void k_wt(const float* __restrict__ wr, const float* __restrict__ wi) {
    __shared__ float sm[64][65];
    int h = blockIdx.x >> 6, i = blockIdx.x & 63, t = threadIdx.x;
    const float* src = wr + (size_t)((h * 64 + i) * 64) * 64;
    float* dst = g_WtR;
#pragma unroll
    for (int pass = 0; pass < 2; pass++) {
#pragma unroll
        for (int r = 0; r < 16; r++) { int u = r * 256 + t; sm[u >> 6][u & 63] = src[u]; }
        __syncthreads();
#pragma unroll
        for (int r = 0; r < 16; r++) {
            int u = r * 256 + t, m = u >> 6, o = u & 63;
            dst[(size_t)((h * 64 + m) * 64 + i) * 64 + o] = sm[o][m];
        }
        __syncthreads();
        src = wi + (size_t)((h * 64 + i) * 64) * 64;
        dst = g_WtI;
    }
}

// ---------------- K1: forward DFT, mma.sync ----------------
// CTA per bh. M=128 modes, N=64 i, K=2048 in 64 chunks of 32. 8 warps 4x2, warp 32x32.
// smem: Ah[2][128][40]b16 @0 (20480), Al @20480, Bh[2][32][72]b16 @40960 (9216), Bl @50176. tot 59392.
__global__ __launch_bounds__(256, 2) void k_fwd(const float* __restrict__ q) {
    extern __shared__ __align__(16) char sm[];
    unsigned sb = s2u(sm);
    int tid = threadIdx.x, lane = tid & 31, w = tid >> 5;
    int bh = blockIdx.x, b = bh >> 3, h = bh & 7;
    const float* qb = q + (size_t)b * NL * 512 + h * 64;
    int wm = w & 3, wn = w >> 2;
    int lq = tid >> 3, iq = (tid & 7) * 8;

    auto stageA = [&](int buf, int l0) {
#pragma unroll
        for (int rpt = 0; rpt < 2; rpt++) {
            int u = rpt * 256 + tid;             // 512 units of 16B
            int m = u >> 2, seg = u & 3;
            unsigned off = (unsigned)buf * 10240 + m * 80 + seg * 16;
            *(uint4*)(sm + off)         = *(const uint4*)(g_FBh + (size_t)m * NL + l0 + seg * 8);
            *(uint4*)(sm + 20480 + off) = *(const uint4*)(g_FBl + (size_t)m * NL + l0 + seg * 8);
        }
    };
    auto stageB = [&](int buf, int l0) {
        const float* src = qb + (size_t)(l0 + lq) * 512 + iq;
        float4 v0 = *(const float4*)src, v1 = *(const float4*)(src + 4);
        unsigned h0, l0w, h1, l1, h2, l2, h3, l3;
        hl2(v0.x, v0.y, h0, l0w); hl2(v0.z, v0.w, h1, l1);
        hl2(v1.x, v1.y, h2, l2);  hl2(v1.z, v1.w, h3, l3);
        unsigned off = (unsigned)buf * 4608 + lq * 144 + iq * 2;
        *(uint4*)(sm + 40960 + off) = make_uint4(h0, h1, h2, h3);
        *(uint4*)(sm + 50176 + off) = make_uint4(l0w, l1, l2, l3);
    };

    float c[2][4][4] = {};
    stageA(0, 0); stageB(0, 0);
    __syncthreads();
    for (int ch = 0; ch < 64; ch++) {
        int buf = ch & 1;
        if (ch + 1 < 64) { stageA(buf ^ 1, (ch + 1) * 32); stageB(buf ^ 1, (ch + 1) * 32); }
#pragma unroll
        for (int ks = 0; ks < 2; ks++) {
            unsigned ah[2][4], al[2][4], bhf[4][2], blf[4][2];
#pragma unroll
            for (int mt = 0; mt < 2; mt++) {
                unsigned row = wm * 32 + mt * 16 + (lane & 7) + ((lane >> 3) & 1) * 8;
                unsigned col = ks * 16 + ((lane >> 4) & 1) * 8;
                unsigned off = (unsigned)buf * 10240 + row * 80 + col * 2;
                ldm_x4(sb + off, ah[mt]);
                ldm_x4(sb + 20480 + off, al[mt]);
            }
#pragma unroll
            for (int nt = 0; nt < 4; nt++) {
                unsigned row = ks * 16 + (lane & 15);
                unsigned off = (unsigned)buf * 4608 + row * 144 + (wn * 32 + nt * 8) * 2;
                ldm_x2t(sb + 40960 + off, bhf[nt]);
                ldm_x2t(sb + 50176 + off, blf[nt]);
            }
#pragma unroll
            for (int mt = 0; mt < 2; mt++)
#pragma unroll
                for (int nt = 0; nt < 4; nt++) {
                    mma_bf16(c[mt][nt], ah[mt], bhf[nt]);
                    mma_bf16(c[mt][nt], ah[mt], blf[nt]);
                    mma_bf16(c[mt][nt], al[mt], bhf[nt]);
                }
        }
        __syncthreads();
    }
    float* xf = g_XF + (size_t)bh * 128 * 64;
#pragma unroll
    for (int mt = 0; mt < 2; mt++) {
        int m0 = wm * 32 + mt * 16 + (lane >> 2);
#pragma unroll
        for (int nt = 0; nt < 4; nt++) {
            int n = wn * 32 + nt * 8 + 2 * (lane & 3);
            *(float2*)&xf[(size_t)m0 * 64 + n]       = make_float2(c[mt][nt][0], c[mt][nt][1]);
            *(float2*)&xf[(size_t)(m0 + 8) * 64 + n] = make_float2(c[mt][nt][2], c[mt][nt][3]);
        }
    }
}

// ---------------- K2: complex mode mixing (128 thr, 4b x 4o tiles, dynamic smem) ----------------
// dyn smem: Xr[64][36] @0 (9216), Xi @9216, Wr[64][64] @18432 (16384), Wi @34816. tot 51200.
__global__ __launch_bounds__(128) void k_mix() {
    extern __shared__ __align__(16) char sm[];
    float* Xr = (float*)sm;                      // [i][b] stride 36
    float* Xi = (float*)(sm + 9216);
    float* Wr = (float*)(sm + 18432);            // [i][o] stride 64
    float* Wi = (float*)(sm + 34816);
    int h = blockIdx.x >> 6, m = blockIdx.x & 63, t = threadIdx.x;
    // stage X transposed: [i][b]
#pragma unroll
    for (int p = 0; p < 16; p++) {
        int u = p * 128 + t;
        int b = u >> 6, i = u & 63;
        size_t base = ((size_t)(b * 8 + h) * 128 + m) * 64;
        Xr[i * 36 + b] = g_XF[base + i];
        Xi[i * 36 + b] = g_XF[base + 4096 + i];
    }
    // stage W: [i][o]
#pragma unroll
    for (int p = 0; p < 32; p++) {
        int u = p * 128 + t, i = u >> 6, o = u & 63;
        size_t base = (size_t)((h * 64 + m) * 64 + i) * 64 + o;
        Wr[i * 64 + o] = g_WtR[base];
        Wi[i * 64 + o] = g_WtI[base];
    }
    __syncthreads();
    int og = (t & 15) * 4, bg = (t >> 4) * 4;    // t>>4 in 0..7
    float ar[4][4], ai[4][4];
#pragma unroll
    for (int j = 0; j < 4; j++)
#pragma unroll
        for (int cc = 0; cc < 4; cc++) { ar[j][cc] = 0.0f; ai[j][cc] = 0.0f; }
    for (int i = 0; i < 64; i++) {
        float4 wr = *(const float4*)&Wr[i * 64 + og];
        float4 wv = *(const float4*)&Wi[i * 64 + og];
        float4 xr = *(const float4*)&Xr[i * 36 + bg];
        float4 xv = *(const float4*)&Xi[i * 36 + bg];
        float wrv[4] = {wr.x, wr.y, wr.z, wr.w}, wvv[4] = {wv.x, wv.y, wv.z, wv.w};
        float xrv[4] = {xr.x, xr.y, xr.z, xr.w}, xvv[4] = {xv.x, xv.y, xv.z, xv.w};
#pragma unroll
        for (int j = 0; j < 4; j++)
#pragma unroll
            for (int cc = 0; cc < 4; cc++) {
                ar[j][cc] += xrv[j] * wrv[cc] - xvv[j] * wvv[cc];
                ai[j][cc] += xrv[j] * wvv[cc] + xvv[j] * wrv[cc];
            }
    }
#pragma unroll
    for (int j = 0; j < 4; j++) {
        int bh = (bg + j) * 8 + h;
        unsigned h0, l0, h1, l1;
        size_t w0 = ((size_t)bh * 128 + m) * 32 + og / 2;
        hl2(ar[j][0], ar[j][1], h0, l0); hl2(ar[j][2], ar[j][3], h1, l1);
        g_O2h[w0] = h0; g_O2h[w0 + 1] = h1; g_O2l[w0] = l0; g_O2l[w0 + 1] = l1;
        size_t w1 = ((size_t)bh * 128 + 64 + m) * 32 + og / 2;
        hl2(ai[j][0], ai[j][1], h0, l0); hl2(ai[j][2], ai[j][3], h1, l1);
        g_O2h[w1] = h0; g_O2h[w1 + 1] = h1; g_O2l[w1] = l0; g_O2l[w1 + 1] = l1;
    }
}

// ---------------- K3: inverse, mma.sync ----------------
// CTA = (bh-group of 4) x (l-tile of 128). M=o(64), N=l(128), K=128. 8 warps 2x4, warp 32x32.
// smem: Bh(IB)[128][136]b16 @0 (34816), Bl @34816, Ah(O2)[128][72]b16 @69632 (18432), Al @88064. tot 106496.
__global__ __launch_bounds__(256, 1) void k_inv(float* __restrict__ out) {
    extern __shared__ __align__(16) char sm[];
    unsigned sb = s2u(sm);
    int tid = threadIdx.x, lane = tid & 31, w = tid >> 5;
    int g = blockIdx.x & 63, lt = blockIdx.x >> 6;
    int wm = w & 1, wn = w >> 1;

    // stage B (IB) once: [128 l][128 k] hi/lo
#pragma unroll
    for (int rpt = 0; rpt < 8; rpt++) {
        int u = rpt * 256 + tid;                 // 2048 units of 16B
        int l = u >> 4, seg = u & 15;
        unsigned off = l * 272 + seg * 16;
        *(uint4*)(sm + off)         = *(const uint4*)(g_IBh + (size_t)(lt * 128 + l) * 128 + seg * 8);
        *(uint4*)(sm + 34816 + off) = *(const uint4*)(g_IBl + (size_t)(lt * 128 + l) * 128 + seg * 8);
    }
    for (int bj = 0; bj < 4; bj++) {
        int bh = g * 4 + bj;
        __syncthreads();                         // A free (prev compute done) / B visible on bj==0
#pragma unroll
        for (int rpt = 0; rpt < 4; rpt++) {
            int u = rpt * 256 + tid;             // 1024 units of 16B
            int k = u >> 3, seg = u & 7;
            unsigned off = k * 144 + seg * 16;
            *(uint4*)(sm + 69632 + off) = *(const uint4*)(g_O2h + (size_t)bh * 4096 + k * 32 + seg * 4);
            *(uint4*)(sm + 88064 + off) = *(const uint4*)(g_O2l + (size_t)bh * 4096 + k * 32 + seg * 4);
        }
        __syncthreads();
        float c[2][4][4] = {};
#pragma unroll
        for (int ks = 0; ks < 8; ks++) {
            int k0 = ks * 16;
            unsigned ah[2][4], al[2][4], bhf[4][2], blf[4][2];
#pragma unroll
            for (int mt = 0; mt < 2; mt++) {
                unsigned row = k0 + (lane & 7) + ((lane >> 4) & 1) * 8;
                unsigned col = wm * 32 + mt * 16 + ((lane >> 3) & 1) * 8;
                unsigned off = row * 144 + col * 2;
                ldm_x4t(sb + 69632 + off, ah[mt]);
                ldm_x4t(sb + 88064 + off, al[mt]);
            }
#pragma unroll
            for (int nt = 0; nt < 4; nt++) {
                unsigned row = wn * 32 + nt * 8 + (lane & 7);
                unsigned col = k0 + ((lane >> 3) & 1) * 8;
                unsigned off = row * 272 + col * 2;
                ldm_x2(sb + off, bhf[nt]);
                ldm_x2(sb + 34816 + off, blf[nt]);
            }
#pragma unroll
            for (int mt = 0; mt < 2; mt++)
#pragma unroll
                for (int nt = 0; nt < 4; nt++) {
                    mma_bf16(c[mt][nt], ah[mt], bhf[nt]);
                    mma_bf16(c[mt][nt], ah[mt], blf[nt]);
                    mma_bf16(c[mt][nt], al[mt], bhf[nt]);
                }
        }
        float* yb = out + (size_t)bh * 64 * NL + lt * 128;
#pragma unroll
        for (int mt = 0; mt < 2; mt++) {
            int o = wm * 32 + mt * 16 + (lane >> 2);
#pragma unroll
            for (int nt = 0; nt < 4; nt++) {
                int l = wn * 32 + nt * 8 + 2 * (lane & 3);
                *(float2*)&yb[(size_t)o * NL + l]       = make_float2(c[mt][nt][0], c[mt][nt][1]);
                *(float2*)&yb[(size_t)(o + 8) * NL + l] = make_float2(c[mt][nt][2], c[mt][nt][3]);
            }
        }
    }
}

// ---------------- launch ----------------
extern "C" void kernel_launch(void* const* d_in, const int* in_sizes, int n_in,
                              void* d_out, int out_size) {
    const float* q     = (const float*)d_in[0];
    const float* wreal = (const float*)d_in[3];
    const float* wimag = (const float*)d_in[4];
    const int*   index = (const int*)d_in[5];
    float* out = (float*)d_out;

    cudaFuncSetAttribute(k_fwd, cudaFuncAttributeMaxDynamicSharedMemorySize, 59392);
    cudaFuncSetAttribute(k_mix, cudaFuncAttributeMaxDynamicSharedMemorySize, 51200);
    cudaFuncSetAttribute(k_inv, cudaFuncAttributeMaxDynamicSharedMemorySize, 106496);

    k_basisF<<<1024, 256>>>(index);
    k_wt<<<512, 256>>>(wreal, wimag);
    k_basisI<<<1024, 256>>>();
    k_fwd<<<256, 256, 59392>>>(q);      // <- profiled slot (launch index 3)
    k_mix<<<512, 128, 51200>>>();
    k_inv<<<1024, 256, 106496>>>(out);
}

// round 12
// speedup vs baseline: 1.0521x; 1.0521x over previous
#include <cuda_runtime.h>
#include <cuda_bf16.h>
#include <cstdint>

// FourierBlock B=32 L=2048 H=8 E=64 M=64 — mma.sync (HMMA) bf16 split version.
//  K1: X[bh][k=128(re|im)][i=64] = FB[k][l] @ q[b,:,h,:]   (K=2048)
//  K2: O2[bh][k][o] complex mix with W (fp32 FFMA), emits bf16 hi/lo [k][o]
//  K3: y[bh][o][l]  = O2^T[o][k] @ IB^T[k][l]              (K=128)
// All big GEMMs: 3-term bf16 hi/lo split (hh + hl + lh), fp32 accumulate.

#define NL 2048

__device__ unsigned short g_FBh[128 * NL], g_FBl[128 * NL];   // [k][l]
__device__ unsigned short g_IBh[NL * 128], g_IBl[NL * 128];   // [l][k]
__device__ float g_WtR[8 * 64 * 64 * 64], g_WtI[8 * 64 * 64 * 64]; // [h][m][i][o]
__device__ float g_XF[256 * 128 * 64];                        // [bh][k][i]
__device__ unsigned g_O2h[256 * 128 * 32], g_O2l[256 * 128 * 32]; // [bh][k][o/2] bf16x2

// ---------------- helpers ----------------
__device__ __forceinline__ unsigned s2u(const void* p) {
    unsigned a;
    asm("{ .reg .u64 t; cvta.to.shared.u64 t, %1; cvt.u32.u64 %0, t; }" : "=r"(a) : "l"(p));
    return a;
}
__device__ __forceinline__ void ldm_x4(unsigned addr, unsigned* r) {
    asm volatile("ldmatrix.sync.aligned.m8n8.x4.shared.b16 {%0,%1,%2,%3}, [%4];"
        : "=r"(r[0]), "=r"(r[1]), "=r"(r[2]), "=r"(r[3]) : "r"(addr));
}
__device__ __forceinline__ void ldm_x4t(unsigned addr, unsigned* r) {
    asm volatile("ldmatrix.sync.aligned.m8n8.x4.trans.shared.b16 {%0,%1,%2,%3}, [%4];"
        : "=r"(r[0]), "=r"(r[1]), "=r"(r[2]), "=r"(r[3]) : "r"(addr));
}
__device__ __forceinline__ void ldm_x2(unsigned addr, unsigned* r) {
    asm volatile("ldmatrix.sync.aligned.m8n8.x2.shared.b16 {%0,%1}, [%2];"
        : "=r"(r[0]), "=r"(r[1]) : "r"(addr));
}
__device__ __forceinline__ void ldm_x2t(unsigned addr, unsigned* r) {
    asm volatile("ldmatrix.sync.aligned.m8n8.x2.trans.shared.b16 {%0,%1}, [%2];"
        : "=r"(r[0]), "=r"(r[1]) : "r"(addr));
}
__device__ __forceinline__ void mma_bf16(float* c, const unsigned* a, const unsigned* b) {
    asm volatile("mma.sync.aligned.m16n8k16.row.col.f32.bf16.bf16.f32 "
        "{%0,%1,%2,%3}, {%4,%5,%6,%7}, {%8,%9}, {%0,%1,%2,%3};"
        : "+f"(c[0]), "+f"(c[1]), "+f"(c[2]), "+f"(c[3])
        : "r"(a[0]), "r"(a[1]), "r"(a[2]), "r"(a[3]), "r"(b[0]), "r"(b[1]));
}
// packed split: (x0,x1) fp32 -> bf16x2 hi word + bf16x2 lo word
__device__ __forceinline__ void hl2(float x0, float x1, unsigned& hw, unsigned& lw) {
    unsigned h;
    asm("cvt.rn.bf16x2.f32 %0, %1, %2;" : "=r"(h) : "f"(x1), "f"(x0)); // hi=x1, lo=x0
    float h0 = __uint_as_float(h << 16);
    float h1 = __uint_as_float(h & 0xffff0000u);
    float l0 = x0 - h0, l1 = x1 - h1;
    asm("cvt.rn.bf16x2.f32 %0, %1, %2;" : "=r"(lw) : "f"(l1), "f"(l0));
    hw = h;
}

// ---------------- K0: fused prep — basis tables + W transpose ----------------
// blocks 0..1023: basis (FB + IB, bf16 hi/lo). blocks 1024..1535: W transpose.
__global__ __launch_bounds__(256) void k_prep(const int* __restrict__ index,
                                              const float* __restrict__ wr,
                                              const float* __restrict__ wi) {
    if (blockIdx.x < 1024) {
        int t = blockIdx.x * 256 + threadIdx.x;    // 0..262143
        float s, c;
        {   // FB [k][l]: k<64 cos, k>=64 -sin, freq=index[k&63]
            int k = t >> 11, l = t & 2047, kf = k & 63;
            int p = (index[kf] * l) & 2047;
            sincospif((float)p * (1.0f / 1024.0f), &s, &c);
            float v = (k < 64) ? c : -s;
            __nv_bfloat16 hb = __float2bfloat16_rn(v);
            g_FBh[t] = __bfloat16_as_ushort(hb);
            g_FBl[t] = __bfloat16_as_ushort(__float2bfloat16_rn(v - __bfloat162float(hb)));
        }
        {   // IB [l][k]: amp-folded irfft basis (modes in slots 0..63)
            int l = t >> 7, k = t & 127, kf = k & 63;
            int p = (kf * l) & 2047;
            sincospif((float)p * (1.0f / 1024.0f), &s, &c);
            float amp = (kf == 0) ? ((k < 64) ? (1.0f / (float)NL) : 0.0f) : (2.0f / (float)NL);
            float v = (k < 64) ? amp * c : -amp * s;
            __nv_bfloat16 hb = __float2bfloat16_rn(v);
            g_IBh[t] = __bfloat16_as_ushort(hb);
            g_IBl[t] = __bfloat16_as_ushort(__float2bfloat16_rn(v - __bfloat162float(hb)));
        }
        return;
    }
    // W transpose [h][i][o][m] -> [h][m][i][o]
    __shared__ float smw[64][65];
    int blk = blockIdx.x - 1024;
    int h = blk >> 6, i = blk & 63, t = threadIdx.x;
    const float* src = wr + (size_t)((h * 64 + i) * 64) * 64;
    float* dst = g_WtR;
#pragma unroll
    for (int pass = 0; pass < 2; pass++) {
#pragma unroll
        for (int r = 0; r < 16; r++) { int u = r * 256 + t; smw[u >> 6][u & 63] = src[u]; }
        __syncthreads();
#pragma unroll
        for (int r = 0; r < 16; r++) {
            int u = r * 256 + t, m = u >> 6, o = u & 63;
            dst[(size_t)((h * 64 + m) * 64 + i) * 64 + o] = smw[o][m];
        }
        __syncthreads();
        src = wi + (size_t)((h * 64 + i) * 64) * 64;
        dst = g_WtI;
    }
}

// ---------------- K1: forward DFT, mma.sync ----------------
// CTA per bh. M=128 modes, N=64 i, K=2048 in 64 chunks of 32. 8 warps 4x2, warp 32x32.
// smem: Ah[2][128][40]b16 @0 (20480), Al @20480, Bh[2][32][72]b16 @40960 (9216), Bl @50176. tot 59392.
// occ target 3 CTAs/SM (24 warps): B-fragments loaded in pairs to keep live regs < 85.
__global__ __launch_bounds__(256, 3) void k_fwd(const float* __restrict__ q) {
    extern __shared__ __align__(16) char sm[];
    unsigned sb = s2u(sm);
    int tid = threadIdx.x, lane = tid & 31, w = tid >> 5;
    int bh = blockIdx.x, b = bh >> 3, h = bh & 7;
    const float* qb = q + (size_t)b * NL * 512 + h * 64;
    int wm = w & 3, wn = w >> 2;
    int lq = tid >> 3, iq = (tid & 7) * 8;

    auto stageA = [&](int buf, int l0) {
#pragma unroll
        for (int rpt = 0; rpt < 2; rpt++) {
            int u = rpt * 256 + tid;             // 512 units of 16B
            int m = u >> 2, seg = u & 3;
            unsigned off = (unsigned)buf * 10240 + m * 80 + seg * 16;
            *(uint4*)(sm + off)         = *(const uint4*)(g_FBh + (size_t)m * NL + l0 + seg * 8);
            *(uint4*)(sm + 20480 + off) = *(const uint4*)(g_FBl + (size_t)m * NL + l0 + seg * 8);
        }
    };
    auto stageB = [&](int buf, int l0) {
        const float* src = qb + (size_t)(l0 + lq) * 512 + iq;
        float4 v0 = *(const float4*)src, v1 = *(const float4*)(src + 4);
        unsigned h0, l0w, h1, l1, h2, l2, h3, l3;
        hl2(v0.x, v0.y, h0, l0w); hl2(v0.z, v0.w, h1, l1);
        hl2(v1.x, v1.y, h2, l2);  hl2(v1.z, v1.w, h3, l3);
        unsigned off = (unsigned)buf * 4608 + lq * 144 + iq * 2;
        *(uint4*)(sm + 40960 + off) = make_uint4(h0, h1, h2, h3);
        *(uint4*)(sm + 50176 + off) = make_uint4(l0w, l1, l2, l3);
    };

    float c[2][4][4] = {};
    stageA(0, 0); stageB(0, 0);
    __syncthreads();
    for (int ch = 0; ch < 64; ch++) {
        int buf = ch & 1;
        if (ch + 1 < 64) { stageA(buf ^ 1, (ch + 1) * 32); stageB(buf ^ 1, (ch + 1) * 32); }
#pragma unroll
        for (int ks = 0; ks < 2; ks++) {
            unsigned ah[2][4], al[2][4];
#pragma unroll
            for (int mt = 0; mt < 2; mt++) {
                unsigned row = wm * 32 + mt * 16 + (lane & 7) + ((lane >> 3) & 1) * 8;
                unsigned col = ks * 16 + ((lane >> 4) & 1) * 8;
                unsigned off = (unsigned)buf * 10240 + row * 80 + col * 2;
                ldm_x4(sb + off, ah[mt]);
                ldm_x4(sb + 20480 + off, al[mt]);
            }
#pragma unroll
            for (int ntp = 0; ntp < 2; ntp++) {       // B frags in pairs: fewer live regs
                unsigned bhf[2][2], blf[2][2];
#pragma unroll
                for (int j = 0; j < 2; j++) {
                    int nt = ntp * 2 + j;
                    unsigned row = ks * 16 + (lane & 15);
                    unsigned off = (unsigned)buf * 4608 + row * 144 + (wn * 32 + nt * 8) * 2;
                    ldm_x2t(sb + 40960 + off, bhf[j]);
                    ldm_x2t(sb + 50176 + off, blf[j]);
                }
#pragma unroll
                for (int mt = 0; mt < 2; mt++)
#pragma unroll
                    for (int j = 0; j < 2; j++) {
                        int nt = ntp * 2 + j;
                        mma_bf16(c[mt][nt], ah[mt], bhf[j]);
                        mma_bf16(c[mt][nt], ah[mt], blf[j]);
                        mma_bf16(c[mt][nt], al[mt], bhf[j]);
                    }
            }
        }
        __syncthreads();
    }
    float* xf = g_XF + (size_t)bh * 128 * 64;
#pragma unroll
    for (int mt = 0; mt < 2; mt++) {
        int m0 = wm * 32 + mt * 16 + (lane >> 2);
#pragma unroll
        for (int nt = 0; nt < 4; nt++) {
            int n = wn * 32 + nt * 8 + 2 * (lane & 3);
            *(float2*)&xf[(size_t)m0 * 64 + n]       = make_float2(c[mt][nt][0], c[mt][nt][1]);
            *(float2*)&xf[(size_t)(m0 + 8) * 64 + n] = make_float2(c[mt][nt][2], c[mt][nt][3]);
        }
    }
}

// ---------------- K2: complex mode mixing (128 thr, 4b x 4o tiles, dynamic smem) ----------------
// dyn smem: Xr[64][36] @0 (9216), Xi @9216, Wr[64][64] @18432 (16384), Wi @34816. tot 51200.
__global__ __launch_bounds__(128) void k_mix() {
    extern __shared__ __align__(16) char sm[];
    float* Xr = (float*)sm;                      // [i][b] stride 36
    float* Xi = (float*)(sm + 9216);
    float* Wr = (float*)(sm + 18432);            // [i][o] stride 64
    float* Wi = (float*)(sm + 34816);
    int h = blockIdx.x >> 6, m = blockIdx.x & 63, t = threadIdx.x;
#pragma unroll
    for (int p = 0; p < 16; p++) {
        int u = p * 128 + t;
        int b = u >> 6, i = u & 63;
        size_t base = ((size_t)(b * 8 + h) * 128 + m) * 64;
        Xr[i * 36 + b] = g_XF[base + i];
        Xi[i * 36 + b] = g_XF[base + 4096 + i];
    }
#pragma unroll
    for (int p = 0; p < 32; p++) {
        int u = p * 128 + t, i = u >> 6, o = u & 63;
        size_t base = (size_t)((h * 64 + m) * 64 + i) * 64 + o;
        Wr[i * 64 + o] = g_WtR[base];
        Wi[i * 64 + o] = g_WtI[base];
    }
    __syncthreads();
    int og = (t & 15) * 4, bg = (t >> 4) * 4;
    float ar[4][4], ai[4][4];
#pragma unroll
    for (int j = 0; j < 4; j++)
#pragma unroll
        for (int cc = 0; cc < 4; cc++) { ar[j][cc] = 0.0f; ai[j][cc] = 0.0f; }
    for (int i = 0; i < 64; i++) {
        float4 wr = *(const float4*)&Wr[i * 64 + og];
        float4 wv = *(const float4*)&Wi[i * 64 + og];
        float4 xr = *(const float4*)&Xr[i * 36 + bg];
        float4 xv = *(const float4*)&Xi[i * 36 + bg];
        float wrv[4] = {wr.x, wr.y, wr.z, wr.w}, wvv[4] = {wv.x, wv.y, wv.z, wv.w};
        float xrv[4] = {xr.x, xr.y, xr.z, xr.w}, xvv[4] = {xv.x, xv.y, xv.z, xv.w};
#pragma unroll
        for (int j = 0; j < 4; j++)
#pragma unroll
            for (int cc = 0; cc < 4; cc++) {
                ar[j][cc] += xrv[j] * wrv[cc] - xvv[j] * wvv[cc];
                ai[j][cc] += xrv[j] * wvv[cc] + xvv[j] * wrv[cc];
            }
    }
#pragma unroll
    for (int j = 0; j < 4; j++) {
        int bh = (bg + j) * 8 + h;
        unsigned h0, l0, h1, l1;
        size_t w0 = ((size_t)bh * 128 + m) * 32 + og / 2;
        hl2(ar[j][0], ar[j][1], h0, l0); hl2(ar[j][2], ar[j][3], h1, l1);
        g_O2h[w0] = h0; g_O2h[w0 + 1] = h1; g_O2l[w0] = l0; g_O2l[w0 + 1] = l1;
        size_t w1 = ((size_t)bh * 128 + 64 + m) * 32 + og / 2;
        hl2(ai[j][0], ai[j][1], h0, l0); hl2(ai[j][2], ai[j][3], h1, l1);
        g_O2h[w1] = h0; g_O2h[w1 + 1] = h1; g_O2l[w1] = l0; g_O2l[w1 + 1] = l1;
    }
}

// ---------------- K3: inverse, mma.sync ----------------
// CTA = (bh-group of 4) x (l-tile of 128). M=o(64), N=l(128), K=128. 8 warps 2x4, warp 32x32.
// smem: Bh(IB)[128][136]b16 @0 (34816), Bl @34816, Ah(O2)[128][72]b16 @69632 (18432), Al @88064. tot 106496.
// occ 2 CTAs/SM: 2x106496 = 213KB fits the 228KB carveout; regs <= 128.
__global__ __launch_bounds__(256, 2) void k_inv(float* __restrict__ out) {
    extern __shared__ __align__(16) char sm[];
    unsigned sb = s2u(sm);
    int tid = threadIdx.x, lane = tid & 31, w = tid >> 5;
    int g = blockIdx.x & 63, lt = blockIdx.x >> 6;
    int wm = w & 1, wn = w >> 1;

    // stage B (IB) once: [128 l][128 k] hi/lo
#pragma unroll
    for (int rpt = 0; rpt < 8; rpt++) {
        int u = rpt * 256 + tid;                 // 2048 units of 16B
        int l = u >> 4, seg = u & 15;
        unsigned off = l * 272 + seg * 16;
        *(uint4*)(sm + off)         = *(const uint4*)(g_IBh + (size_t)(lt * 128 + l) * 128 + seg * 8);
        *(uint4*)(sm + 34816 + off) = *(const uint4*)(g_IBl + (size_t)(lt * 128 + l) * 128 + seg * 8);
    }
    for (int bj = 0; bj < 4; bj++) {
        int bh = g * 4 + bj;
        __syncthreads();                         // A free (prev compute done) / B visible on bj==0
#pragma unroll
        for (int rpt = 0; rpt < 4; rpt++) {
            int u = rpt * 256 + tid;             // 1024 units of 16B
            int k = u >> 3, seg = u & 7;
            unsigned off = k * 144 + seg * 16;
            *(uint4*)(sm + 69632 + off) = *(const uint4*)(g_O2h + (size_t)bh * 4096 + k * 32 + seg * 4);
            *(uint4*)(sm + 88064 + off) = *(const uint4*)(g_O2l + (size_t)bh * 4096 + k * 32 + seg * 4);
        }
        __syncthreads();
        float c[2][4][4] = {};
#pragma unroll
        for (int ks = 0; ks < 8; ks++) {
            int k0 = ks * 16;
            unsigned ah[2][4], al[2][4];
#pragma unroll
            for (int mt = 0; mt < 2; mt++) {
                unsigned row = k0 + (lane & 7) + ((lane >> 4) & 1) * 8;
                unsigned col = wm * 32 + mt * 16 + ((lane >> 3) & 1) * 8;
                unsigned off = row * 144 + col * 2;
                ldm_x4t(sb + 69632 + off, ah[mt]);
                ldm_x4t(sb + 88064 + off, al[mt]);
            }
#pragma unroll
            for (int ntp = 0; ntp < 2; ntp++) {
                unsigned bhf[2][2], blf[2][2];
#pragma unroll
                for (int j = 0; j < 2; j++) {
                    int nt = ntp * 2 + j;
                    unsigned row = wn * 32 + nt * 8 + (lane & 7);
                    unsigned col = k0 + ((lane >> 3) & 1) * 8;
                    unsigned off = row * 272 + col * 2;
                    ldm_x2(sb + off, bhf[j]);
                    ldm_x2(sb + 34816 + off, blf[j]);
                }
#pragma unroll
                for (int mt = 0; mt < 2; mt++)
#pragma unroll
                    for (int j = 0; j < 2; j++) {
                        int nt = ntp * 2 + j;
                        mma_bf16(c[mt][nt], ah[mt], bhf[j]);
                        mma_bf16(c[mt][nt], ah[mt], blf[j]);
                        mma_bf16(c[mt][nt], al[mt], bhf[j]);
                    }
            }
        }
        float* yb = out + (size_t)bh * 64 * NL + lt * 128;
#pragma unroll
        for (int mt = 0; mt < 2; mt++) {
            int o = wm * 32 + mt * 16 + (lane >> 2);
#pragma unroll
            for (int nt = 0; nt < 4; nt++) {
                int l = wn * 32 + nt * 8 + 2 * (lane & 3);
                *(float2*)&yb[(size_t)o * NL + l]       = make_float2(c[mt][nt][0], c[mt][nt][1]);
                *(float2*)&yb[(size_t)(o + 8) * NL + l] = make_float2(c[mt][nt][2], c[mt][nt][3]);
            }
        }
    }
}

// ---------------- launch ----------------
extern "C" void kernel_launch(void* const* d_in, const int* in_sizes, int n_in,
                              void* d_out, int out_size) {
    const float* q     = (const float*)d_in[0];
    const float* wreal = (const float*)d_in[3];
    const float* wimag = (const float*)d_in[4];
    const int*   index = (const int*)d_in[5];
    float* out = (float*)d_out;

    cudaFuncSetAttribute(k_fwd, cudaFuncAttributeMaxDynamicSharedMemorySize, 59392);
    cudaFuncSetAttribute(k_mix, cudaFuncAttributeMaxDynamicSharedMemorySize, 51200);
    cudaFuncSetAttribute(k_inv, cudaFuncAttributeMaxDynamicSharedMemorySize, 106496);

    k_prep<<<1536, 256>>>(index, wreal, wimag);   // launch 0
    k_fwd<<<256, 256, 59392>>>(q);                // launch 1
    k_mix<<<512, 128, 51200>>>();                 // launch 2
    k_inv<<<1024, 256, 106496>>>(out);            // launch 3  <- profiled slot
}

// round 13
// speedup vs baseline: 1.2061x; 1.1464x over previous
#include <cuda_runtime.h>
#include <cuda_bf16.h>
#include <cstdint>

// FourierBlock B=32 L=2048 H=8 E=64 M=64 — mma.sync (HMMA) bf16 split version.
//  K1: X[bh][k=128(re|im)][i=64] = FB[k][l] @ q[b,:,h,:]   (K=2048)
//  K2: O2[bh][k][o] complex mix with W (fp32 FFMA), emits bf16 hi/lo [k][o]
//  K3: y[bh][o][l]  = O2^T[o][k] @ IB^T[k][l]              (K=128)
// All big GEMMs: 3-term bf16 hi/lo split (hh + hl + lh), fp32 accumulate.
// R13: software pipelining — LDG-to-register prefetch overlapped with MMA compute.

#define NL 2048

__device__ unsigned short g_FBh[128 * NL], g_FBl[128 * NL];   // [k][l]
__device__ unsigned short g_IBh[NL * 128], g_IBl[NL * 128];   // [l][k]
__device__ float g_WtR[8 * 64 * 64 * 64], g_WtI[8 * 64 * 64 * 64]; // [h][m][i][o]
__device__ float g_XF[256 * 128 * 64];                        // [bh][k][i]
__device__ unsigned g_O2h[256 * 128 * 32], g_O2l[256 * 128 * 32]; // [bh][k][o/2] bf16x2

// ---------------- helpers ----------------
__device__ __forceinline__ unsigned s2u(const void* p) {
    unsigned a;
    asm("{ .reg .u64 t; cvta.to.shared.u64 t, %1; cvt.u32.u64 %0, t; }" : "=r"(a) : "l"(p));
    return a;
}
__device__ __forceinline__ void ldm_x4(unsigned addr, unsigned* r) {
    asm volatile("ldmatrix.sync.aligned.m8n8.x4.shared.b16 {%0,%1,%2,%3}, [%4];"
        : "=r"(r[0]), "=r"(r[1]), "=r"(r[2]), "=r"(r[3]) : "r"(addr));
}
__device__ __forceinline__ void ldm_x4t(unsigned addr, unsigned* r) {
    asm volatile("ldmatrix.sync.aligned.m8n8.x4.trans.shared.b16 {%0,%1,%2,%3}, [%4];"
        : "=r"(r[0]), "=r"(r[1]), "=r"(r[2]), "=r"(r[3]) : "r"(addr));
}
__device__ __forceinline__ void ldm_x2(unsigned addr, unsigned* r) {
    asm volatile("ldmatrix.sync.aligned.m8n8.x2.shared.b16 {%0,%1}, [%2];"
        : "=r"(r[0]), "=r"(r[1]) : "r"(addr));
}
__device__ __forceinline__ void ldm_x2t(unsigned addr, unsigned* r) {
    asm volatile("ldmatrix.sync.aligned.m8n8.x2.trans.shared.b16 {%0,%1}, [%2];"
        : "=r"(r[0]), "=r"(r[1]) : "r"(addr));
}
__device__ __forceinline__ void mma_bf16(float* c, const unsigned* a, const unsigned* b) {
    asm volatile("mma.sync.aligned.m16n8k16.row.col.f32.bf16.bf16.f32 "
        "{%0,%1,%2,%3}, {%4,%5,%6,%7}, {%8,%9}, {%0,%1,%2,%3};"
        : "+f"(c[0]), "+f"(c[1]), "+f"(c[2]), "+f"(c[3])
        : "r"(a[0]), "r"(a[1]), "r"(a[2]), "r"(a[3]), "r"(b[0]), "r"(b[1]));
}
// packed split: (x0,x1) fp32 -> bf16x2 hi word + bf16x2 lo word
__device__ __forceinline__ void hl2(float x0, float x1, unsigned& hw, unsigned& lw) {
    unsigned h;
    asm("cvt.rn.bf16x2.f32 %0, %1, %2;" : "=r"(h) : "f"(x1), "f"(x0)); // hi=x1, lo=x0
    float h0 = __uint_as_float(h << 16);
    float h1 = __uint_as_float(h & 0xffff0000u);
    float l0 = x0 - h0, l1 = x1 - h1;
    asm("cvt.rn.bf16x2.f32 %0, %1, %2;" : "=r"(lw) : "f"(l1), "f"(l0));
    hw = h;
}

// ---------------- K0: fused prep — basis tables + W transpose ----------------
__global__ __launch_bounds__(256) void k_prep(const int* __restrict__ index,
                                              const float* __restrict__ wr,
                                              const float* __restrict__ wi) {
    if (blockIdx.x < 1024) {
        int t = blockIdx.x * 256 + threadIdx.x;    // 0..262143
        float s, c;
        {   // FB [k][l]: k<64 cos, k>=64 -sin, freq=index[k&63]
            int k = t >> 11, l = t & 2047, kf = k & 63;
            int p = (index[kf] * l) & 2047;
            sincospif((float)p * (1.0f / 1024.0f), &s, &c);
            float v = (k < 64) ? c : -s;
            __nv_bfloat16 hb = __float2bfloat16_rn(v);
            g_FBh[t] = __bfloat16_as_ushort(hb);
            g_FBl[t] = __bfloat16_as_ushort(__float2bfloat16_rn(v - __bfloat162float(hb)));
        }
        {   // IB [l][k]: amp-folded irfft basis (modes in slots 0..63)
            int l = t >> 7, k = t & 127, kf = k & 63;
            int p = (kf * l) & 2047;
            sincospif((float)p * (1.0f / 1024.0f), &s, &c);
            float amp = (kf == 0) ? ((k < 64) ? (1.0f / (float)NL) : 0.0f) : (2.0f / (float)NL);
            float v = (k < 64) ? amp * c : -amp * s;
            __nv_bfloat16 hb = __float2bfloat16_rn(v);
            g_IBh[t] = __bfloat16_as_ushort(hb);
            g_IBl[t] = __bfloat16_as_ushort(__float2bfloat16_rn(v - __bfloat162float(hb)));
        }
        return;
    }
    // W transpose [h][i][o][m] -> [h][m][i][o]
    __shared__ float smw[64][65];
    int blk = blockIdx.x - 1024;
    int h = blk >> 6, i = blk & 63, t = threadIdx.x;
    const float* src = wr + (size_t)((h * 64 + i) * 64) * 64;
    float* dst = g_WtR;
#pragma unroll
    for (int pass = 0; pass < 2; pass++) {
#pragma unroll
        for (int r = 0; r < 16; r++) { int u = r * 256 + t; smw[u >> 6][u & 63] = src[u]; }
        __syncthreads();
#pragma unroll
        for (int r = 0; r < 16; r++) {
            int u = r * 256 + t, m = u >> 6, o = u & 63;
            dst[(size_t)((h * 64 + m) * 64 + i) * 64 + o] = smw[o][m];
        }
        __syncthreads();
        src = wi + (size_t)((h * 64 + i) * 64) * 64;
        dst = g_WtI;
    }
}

// ---------------- K1: forward DFT, mma.sync, reg-prefetch pipeline ----------------
// CTA per bh. M=128 modes, N=64 i, K=2048 in 64 chunks of 32. 8 warps 4x2, warp 32x32.
// smem: Ah[2][128][40]b16 @0 (20480), Al @20480, Bh[2][32][72]b16 @40960 (9216), Bl @50176. tot 59392.
__global__ __launch_bounds__(256, 2) void k_fwd(const float* __restrict__ q) {
    extern __shared__ __align__(16) char sm[];
    unsigned sb = s2u(sm);
    int tid = threadIdx.x, lane = tid & 31, w = tid >> 5;
    int bh = blockIdx.x, b = bh >> 3, h = bh & 7;
    const float* qb = q + (size_t)b * NL * 512 + h * 64;
    int wm = w & 3, wn = w >> 2;
    int lq = tid >> 3, iq = (tid & 7) * 8;

    uint4 pA[4];    // FBh rpt0, FBl rpt0, FBh rpt1, FBl rpt1
    float4 pB[2];

    auto loadAB = [&](int l0) {
#pragma unroll
        for (int rpt = 0; rpt < 2; rpt++) {
            int u = rpt * 256 + tid;
            int m = u >> 2, seg = u & 3;
            pA[rpt * 2]     = *(const uint4*)(g_FBh + (size_t)m * NL + l0 + seg * 8);
            pA[rpt * 2 + 1] = *(const uint4*)(g_FBl + (size_t)m * NL + l0 + seg * 8);
        }
        const float* src = qb + (size_t)(l0 + lq) * 512 + iq;
        pB[0] = *(const float4*)src;
        pB[1] = *(const float4*)(src + 4);
    };
    auto storeAB = [&](int buf) {
#pragma unroll
        for (int rpt = 0; rpt < 2; rpt++) {
            int u = rpt * 256 + tid;
            int m = u >> 2, seg = u & 3;
            unsigned off = (unsigned)buf * 10240 + m * 80 + seg * 16;
            *(uint4*)(sm + off)         = pA[rpt * 2];
            *(uint4*)(sm + 20480 + off) = pA[rpt * 2 + 1];
        }
        unsigned h0, l0w, h1, l1, h2, l2, h3, l3;
        hl2(pB[0].x, pB[0].y, h0, l0w); hl2(pB[0].z, pB[0].w, h1, l1);
        hl2(pB[1].x, pB[1].y, h2, l2);  hl2(pB[1].z, pB[1].w, h3, l3);
        unsigned off = (unsigned)buf * 4608 + lq * 144 + iq * 2;
        *(uint4*)(sm + 40960 + off) = make_uint4(h0, h1, h2, h3);
        *(uint4*)(sm + 50176 + off) = make_uint4(l0w, l1, l2, l3);
    };

    float c[2][4][4] = {};
    loadAB(0);
    storeAB(0);
    __syncthreads();
    for (int ch = 0; ch < 64; ch++) {
        int buf = ch & 1;
        if (ch + 1 < 64) loadAB((ch + 1) * 32);        // LDG issued; latency hidden by compute
#pragma unroll
        for (int ks = 0; ks < 2; ks++) {
            unsigned ah[2][4], al[2][4];
#pragma unroll
            for (int mt = 0; mt < 2; mt++) {
                unsigned row = wm * 32 + mt * 16 + (lane & 7) + ((lane >> 3) & 1) * 8;
                unsigned col = ks * 16 + ((lane >> 4) & 1) * 8;
                unsigned off = (unsigned)buf * 10240 + row * 80 + col * 2;
                ldm_x4(sb + off, ah[mt]);
                ldm_x4(sb + 20480 + off, al[mt]);
            }
#pragma unroll
            for (int ntp = 0; ntp < 2; ntp++) {
                unsigned bhf[2][2], blf[2][2];
#pragma unroll
                for (int j = 0; j < 2; j++) {
                    int nt = ntp * 2 + j;
                    unsigned row = ks * 16 + (lane & 15);
                    unsigned off = (unsigned)buf * 4608 + row * 144 + (wn * 32 + nt * 8) * 2;
                    ldm_x2t(sb + 40960 + off, bhf[j]);
                    ldm_x2t(sb + 50176 + off, blf[j]);
                }
#pragma unroll
                for (int mt = 0; mt < 2; mt++)
#pragma unroll
                    for (int j = 0; j < 2; j++) {
                        int nt = ntp * 2 + j;
                        mma_bf16(c[mt][nt], ah[mt], bhf[j]);
                        mma_bf16(c[mt][nt], ah[mt], blf[j]);
                        mma_bf16(c[mt][nt], al[mt], bhf[j]);
                    }
            }
        }
        if (ch + 1 < 64) storeAB(buf ^ 1);             // consumes prefetch; mostly arrived
        __syncthreads();
    }
    float* xf = g_XF + (size_t)bh * 128 * 64;
#pragma unroll
    for (int mt = 0; mt < 2; mt++) {
        int m0 = wm * 32 + mt * 16 + (lane >> 2);
#pragma unroll
        for (int nt = 0; nt < 4; nt++) {
            int n = wn * 32 + nt * 8 + 2 * (lane & 3);
            *(float2*)&xf[(size_t)m0 * 64 + n]       = make_float2(c[mt][nt][0], c[mt][nt][1]);
            *(float2*)&xf[(size_t)(m0 + 8) * 64 + n] = make_float2(c[mt][nt][2], c[mt][nt][3]);
        }
    }
}

// ---------------- K2: complex mode mixing (128 thr, 4b x 4o tiles, dynamic smem) ----------------
// dyn smem: Xr[64][36] @0 (9216), Xi @9216, Wr[64][64] @18432 (16384), Wi @34816. tot 51200.
__global__ __launch_bounds__(128) void k_mix() {
    extern __shared__ __align__(16) char sm[];
    float* Xr = (float*)sm;                      // [i][b] stride 36
    float* Xi = (float*)(sm + 9216);
    float* Wr = (float*)(sm + 18432);            // [i][o] stride 64
    float* Wi = (float*)(sm + 34816);
    int h = blockIdx.x >> 6, m = blockIdx.x & 63, t = threadIdx.x;
#pragma unroll
    for (int p = 0; p < 16; p++) {
        int u = p * 128 + t;
        int b = u >> 6, i = u & 63;
        size_t base = ((size_t)(b * 8 + h) * 128 + m) * 64;
        Xr[i * 36 + b] = g_XF[base + i];
        Xi[i * 36 + b] = g_XF[base + 4096 + i];
    }
#pragma unroll
    for (int p = 0; p < 32; p++) {
        int u = p * 128 + t, i = u >> 6, o = u & 63;
        size_t base = (size_t)((h * 64 + m) * 64 + i) * 64 + o;
        Wr[i * 64 + o] = g_WtR[base];
        Wi[i * 64 + o] = g_WtI[base];
    }
    __syncthreads();
    int og = (t & 15) * 4, bg = (t >> 4) * 4;
    float ar[4][4], ai[4][4];
#pragma unroll
    for (int j = 0; j < 4; j++)
#pragma unroll
        for (int cc = 0; cc < 4; cc++) { ar[j][cc] = 0.0f; ai[j][cc] = 0.0f; }
    for (int i = 0; i < 64; i++) {
        float4 wr = *(const float4*)&Wr[i * 64 + og];
        float4 wv = *(const float4*)&Wi[i * 64 + og];
        float4 xr = *(const float4*)&Xr[i * 36 + bg];
        float4 xv = *(const float4*)&Xi[i * 36 + bg];
        float wrv[4] = {wr.x, wr.y, wr.z, wr.w}, wvv[4] = {wv.x, wv.y, wv.z, wv.w};
        float xrv[4] = {xr.x, xr.y, xr.z, xr.w}, xvv[4] = {xv.x, xv.y, xv.z, xv.w};
#pragma unroll
        for (int j = 0; j < 4; j++)
#pragma unroll
            for (int cc = 0; cc < 4; cc++) {
                ar[j][cc] += xrv[j] * wrv[cc] - xvv[j] * wvv[cc];
                ai[j][cc] += xrv[j] * wvv[cc] + xvv[j] * wrv[cc];
            }
    }
#pragma unroll
    for (int j = 0; j < 4; j++) {
        int bh = (bg + j) * 8 + h;
        unsigned h0, l0, h1, l1;
        size_t w0 = ((size_t)bh * 128 + m) * 32 + og / 2;
        hl2(ar[j][0], ar[j][1], h0, l0); hl2(ar[j][2], ar[j][3], h1, l1);
        g_O2h[w0] = h0; g_O2h[w0 + 1] = h1; g_O2l[w0] = l0; g_O2l[w0 + 1] = l1;
        size_t w1 = ((size_t)bh * 128 + 64 + m) * 32 + og / 2;
        hl2(ai[j][0], ai[j][1], h0, l0); hl2(ai[j][2], ai[j][3], h1, l1);
        g_O2h[w1] = h0; g_O2h[w1 + 1] = h1; g_O2l[w1] = l0; g_O2l[w1 + 1] = l1;
    }
}

// ---------------- K3: inverse, mma.sync, reg-prefetch pipeline ----------------
// CTA = (bh-group of 4) x (l-tile of 128). M=o(64), N=l(128), K=128. 8 warps 2x4, warp 32x32.
// smem: Bh(IB)[128][136]b16 @0 (34816), Bl @34816, Ah(O2)[128][72]b16 @69632 (18432), Al @88064. tot 106496.
__global__ __launch_bounds__(256, 2) void k_inv(float* __restrict__ out) {
    extern __shared__ __align__(16) char sm[];
    unsigned sb = s2u(sm);
    int tid = threadIdx.x, lane = tid & 31, w = tid >> 5;
    int g = blockIdx.x & 63, lt = blockIdx.x >> 6;
    int wm = w & 1, wn = w >> 1;

    // stage B (IB) once: [128 l][128 k] hi/lo
#pragma unroll
    for (int rpt = 0; rpt < 8; rpt++) {
        int u = rpt * 256 + tid;                 // 2048 units of 16B
        int l = u >> 4, seg = u & 15;
        unsigned off = l * 272 + seg * 16;
        *(uint4*)(sm + off)         = *(const uint4*)(g_IBh + (size_t)(lt * 128 + l) * 128 + seg * 8);
        *(uint4*)(sm + 34816 + off) = *(const uint4*)(g_IBl + (size_t)(lt * 128 + l) * 128 + seg * 8);
    }

    uint4 pH[4], pL[4];
    auto loadO2 = [&](int bh) {
#pragma unroll
        for (int rpt = 0; rpt < 4; rpt++) {
            int u = rpt * 256 + tid;
            int k = u >> 3, seg = u & 7;
            pH[rpt] = *(const uint4*)(g_O2h + (size_t)bh * 4096 + k * 32 + seg * 4);
            pL[rpt] = *(const uint4*)(g_O2l + (size_t)bh * 4096 + k * 32 + seg * 4);
        }
    };
    loadO2(g * 4);

    for (int bj = 0; bj < 4; bj++) {
        int bh = g * 4 + bj;
        __syncthreads();                         // prev compute done (A region free)
#pragma unroll
        for (int rpt = 0; rpt < 4; rpt++) {
            int u = rpt * 256 + tid;
            int k = u >> 3, seg = u & 7;
            unsigned off = k * 144 + seg * 16;
            *(uint4*)(sm + 69632 + off) = pH[rpt];
            *(uint4*)(sm + 88064 + off) = pL[rpt];
        }
        __syncthreads();
        if (bj < 3) loadO2(bh + 1);              // LDG issued; latency hidden by compute
        float c[2][4][4] = {};
#pragma unroll
        for (int ks = 0; ks < 8; ks++) {
            int k0 = ks * 16;
            unsigned ah[2][4], al[2][4];
#pragma unroll
            for (int mt = 0; mt < 2; mt++) {
                unsigned row = k0 + (lane & 7) + ((lane >> 4) & 1) * 8;
                unsigned col = wm * 32 + mt * 16 + ((lane >> 3) & 1) * 8;
                unsigned off = row * 144 + col * 2;
                ldm_x4t(sb + 69632 + off, ah[mt]);
                ldm_x4t(sb + 88064 + off, al[mt]);
            }
#pragma unroll
            for (int ntp = 0; ntp < 2; ntp++) {
                unsigned bhf[2][2], blf[2][2];
#pragma unroll
                for (int j = 0; j < 2; j++) {
                    int nt = ntp * 2 + j;
                    unsigned row = wn * 32 + nt * 8 + (lane & 7);
                    unsigned col = k0 + ((lane >> 3) & 1) * 8;
                    unsigned off = row * 272 + col * 2;
                    ldm_x2(sb + off, bhf[j]);
                    ldm_x2(sb + 34816 + off, blf[j]);
                }
#pragma unroll
                for (int mt = 0; mt < 2; mt++)
#pragma unroll
                    for (int j = 0; j < 2; j++) {
                        int nt = ntp * 2 + j;
                        mma_bf16(c[mt][nt], ah[mt], bhf[j]);
                        mma_bf16(c[mt][nt], ah[mt], blf[j]);
                        mma_bf16(c[mt][nt], al[mt], bhf[j]);
                    }
            }
        }
        float* yb = out + (size_t)bh * 64 * NL + lt * 128;
#pragma unroll
        for (int mt = 0; mt < 2; mt++) {
            int o = wm * 32 + mt * 16 + (lane >> 2);
#pragma unroll
            for (int nt = 0; nt < 4; nt++) {
                int l = wn * 32 + nt * 8 + 2 * (lane & 3);
                *(float2*)&yb[(size_t)o * NL + l]       = make_float2(c[mt][nt][0], c[mt][nt][1]);
                *(float2*)&yb[(size_t)(o + 8) * NL + l] = make_float2(c[mt][nt][2], c[mt][nt][3]);
            }
        }
    }
}

// ---------------- launch ----------------
extern "C" void kernel_launch(void* const* d_in, const int* in_sizes, int n_in,
                              void* d_out, int out_size) {
    const float* q     = (const float*)d_in[0];
    const float* wreal = (const float*)d_in[3];
    const float* wimag = (const float*)d_in[4];
    const int*   index = (const int*)d_in[5];
    float* out = (float*)d_out;

    cudaFuncSetAttribute(k_fwd, cudaFuncAttributeMaxDynamicSharedMemorySize, 59392);
    cudaFuncSetAttribute(k_mix, cudaFuncAttributeMaxDynamicSharedMemorySize, 51200);
    cudaFuncSetAttribute(k_inv, cudaFuncAttributeMaxDynamicSharedMemorySize, 106496);

    k_prep<<<1536, 256>>>(index, wreal, wimag);   // launch 0
    k_fwd<<<256, 256, 59392>>>(q);                // launch 1
    k_mix<<<512, 128, 51200>>>();                 // launch 2
    k_inv<<<1024, 256, 106496>>>(out);            // launch 3  <- profiled slot
}

// round 14
// speedup vs baseline: 1.2404x; 1.0284x over previous
#include <cuda_runtime.h>
#include <cuda_bf16.h>
#include <cstdint>

// FourierBlock B=32 L=2048 H=8 E=64 M=64 — mma.sync (HMMA) bf16 split version.
//  K1: X[bh][k=128(re|im)][i] = FB[k][l] @ q   (2 heads/CTA, N=128, K-split x2, cp.async A)
//  K2: O2[bh][k][o] complex mix (sums K-parts), emits bf16 hi/lo [k][o]
//  K3: y[bh][o][l]  = O2^T[o][k] @ IB^T[k][l]  (K=128, reg-prefetch pipeline)
// All big GEMMs: 3-term bf16 hi/lo split (hh + hl + lh), fp32 accumulate.

#define NL 2048
#define XPART (256 * 128 * 64)

__device__ unsigned short g_FBh[128 * NL], g_FBl[128 * NL];   // [k][l]
__device__ unsigned short g_IBh[NL * 128], g_IBl[NL * 128];   // [l][k]
__device__ float g_WtR[8 * 64 * 64 * 64], g_WtI[8 * 64 * 64 * 64]; // [h][m][i][o]
__device__ float g_XF[2 * XPART];                             // [part][bh][k][i]
__device__ unsigned g_O2h[256 * 128 * 32], g_O2l[256 * 128 * 32]; // [bh][k][o/2] bf16x2

// ---------------- helpers ----------------
__device__ __forceinline__ unsigned s2u(const void* p) {
    unsigned a;
    asm("{ .reg .u64 t; cvta.to.shared.u64 t, %1; cvt.u32.u64 %0, t; }" : "=r"(a) : "l"(p));
    return a;
}
__device__ __forceinline__ void cpa16(unsigned daddr, const void* gptr) {
    asm volatile("cp.async.cg.shared.global [%0], [%1], 16;" :: "r"(daddr), "l"(gptr) : "memory");
}
__device__ __forceinline__ void cpa_commit() { asm volatile("cp.async.commit_group;" ::: "memory"); }
__device__ __forceinline__ void cpa_wait0() { asm volatile("cp.async.wait_group 0;" ::: "memory"); }
__device__ __forceinline__ void ldm_x4(unsigned addr, unsigned* r) {
    asm volatile("ldmatrix.sync.aligned.m8n8.x4.shared.b16 {%0,%1,%2,%3}, [%4];"
        : "=r"(r[0]), "=r"(r[1]), "=r"(r[2]), "=r"(r[3]) : "r"(addr));
}
__device__ __forceinline__ void ldm_x4t(unsigned addr, unsigned* r) {
    asm volatile("ldmatrix.sync.aligned.m8n8.x4.trans.shared.b16 {%0,%1,%2,%3}, [%4];"
        : "=r"(r[0]), "=r"(r[1]), "=r"(r[2]), "=r"(r[3]) : "r"(addr));
}
__device__ __forceinline__ void ldm_x2(unsigned addr, unsigned* r) {
    asm volatile("ldmatrix.sync.aligned.m8n8.x2.shared.b16 {%0,%1}, [%2];"
        : "=r"(r[0]), "=r"(r[1]) : "r"(addr));
}
__device__ __forceinline__ void ldm_x2t(unsigned addr, unsigned* r) {
    asm volatile("ldmatrix.sync.aligned.m8n8.x2.trans.shared.b16 {%0,%1}, [%2];"
        : "=r"(r[0]), "=r"(r[1]) : "r"(addr));
}
__device__ __forceinline__ void mma_bf16(float* c, const unsigned* a, const unsigned* b) {
    asm volatile("mma.sync.aligned.m16n8k16.row.col.f32.bf16.bf16.f32 "
        "{%0,%1,%2,%3}, {%4,%5,%6,%7}, {%8,%9}, {%0,%1,%2,%3};"
        : "+f"(c[0]), "+f"(c[1]), "+f"(c[2]), "+f"(c[3])
        : "r"(a[0]), "r"(a[1]), "r"(a[2]), "r"(a[3]), "r"(b[0]), "r"(b[1]));
}
// packed split: (x0,x1) fp32 -> bf16x2 hi word + bf16x2 lo word
__device__ __forceinline__ void hl2(float x0, float x1, unsigned& hw, unsigned& lw) {
    unsigned h;
    asm("cvt.rn.bf16x2.f32 %0, %1, %2;" : "=r"(h) : "f"(x1), "f"(x0)); // hi=x1, lo=x0
    float h0 = __uint_as_float(h << 16);
    float h1 = __uint_as_float(h & 0xffff0000u);
    float l0 = x0 - h0, l1 = x1 - h1;
    asm("cvt.rn.bf16x2.f32 %0, %1, %2;" : "=r"(lw) : "f"(l1), "f"(l0));
    hw = h;
}

// ---------------- K0a: forward basis ----------------
__global__ __launch_bounds__(256) void k_basisF(const int* __restrict__ index) {
    int t = blockIdx.x * 256 + threadIdx.x;
    int k = t >> 11, l = t & 2047, kf = k & 63;
    int p = (index[kf] * l) & 2047;
    float s, c;
    sincospif((float)p * (1.0f / 1024.0f), &s, &c);
    float v = (k < 64) ? c : -s;
    __nv_bfloat16 hb = __float2bfloat16_rn(v);
    g_FBh[t] = __bfloat16_as_ushort(hb);
    g_FBl[t] = __bfloat16_as_ushort(__float2bfloat16_rn(v - __bfloat162float(hb)));
}
// ---------------- K0c: inverse basis ----------------
__global__ __launch_bounds__(256) void k_basisI() {
    int t = blockIdx.x * 256 + threadIdx.x;
    int l = t >> 7, k = t & 127, kf = k & 63;
    int p = (kf * l) & 2047;
    float s, c;
    sincospif((float)p * (1.0f / 1024.0f), &s, &c);
    float amp = (kf == 0) ? ((k < 64) ? (1.0f / (float)NL) : 0.0f) : (2.0f / (float)NL);
    float v = (k < 64) ? amp * c : -amp * s;
    __nv_bfloat16 hb = __float2bfloat16_rn(v);
    g_IBh[t] = __bfloat16_as_ushort(hb);
    g_IBl[t] = __bfloat16_as_ushort(__float2bfloat16_rn(v - __bfloat162float(hb)));
}
// ---------------- K0b: W transpose [h][i][o][m] -> [h][m][i][o] ----------------
__global__ __launch_bounds__(256) void k_wt(const float* __restrict__ wr, const float* __restrict__ wi) {
    __shared__ float smw[64][65];
    int h = blockIdx.x >> 6, i = blockIdx.x & 63, t = threadIdx.x;
    const float* src = wr + (size_t)((h * 64 + i) * 64) * 64;
    float* dst = g_WtR;
#pragma unroll
    for (int pass = 0; pass < 2; pass++) {
#pragma unroll
        for (int r = 0; r < 16; r++) { int u = r * 256 + t; smw[u >> 6][u & 63] = src[u]; }
        __syncthreads();
#pragma unroll
        for (int r = 0; r < 16; r++) {
            int u = r * 256 + t, m = u >> 6, o = u & 63;
            dst[(size_t)((h * 64 + m) * 64 + i) * 64 + o] = smw[o][m];
        }
        __syncthreads();
        src = wi + (size_t)((h * 64 + i) * 64) * 64;
        dst = g_WtI;
    }
}

// ---------------- K1: forward DFT, 2 heads/CTA, warp 32x64, K-split x2 ----------------
// grid 256: p = blk>>7 (K half), bhp = blk&127 (b = >>2, hp = &3).
// CTA tile: M=128 modes x N=128 (heads 2hp, 2hp+1). 8 warps 4x2, warp 32x64.
// smem: Ah[2][128][80B] @0 (20480) | Al @20480 | Bh[2][32][272B] @40960 (17408) | Bl @58368. tot 75776.
__global__ __launch_bounds__(256, 2) void k_fwd(const float* __restrict__ q) {
    extern __shared__ __align__(16) char sm[];
    unsigned sb = s2u(sm);
    int tid = threadIdx.x, lane = tid & 31, w = tid >> 5;
    int p = blockIdx.x >> 7, bhp = blockIdx.x & 127;
    int b = bhp >> 2, hp = bhp & 3;
    const float* qb = q + (size_t)b * NL * 512 + hp * 128;
    int wm = w & 3, wn = w >> 2;
    int lq = tid >> 3, iq = (tid & 7) * 16;      // iq: float offset within 128 channels
    int base = p * 1024;

    auto stageA_async = [&](int buf, int l0) {
#pragma unroll
        for (int rpt = 0; rpt < 2; rpt++) {
            int u = rpt * 256 + tid;             // 512 units of 16B per hi/lo
            int m = u >> 2, seg = u & 3;
            unsigned off = (unsigned)buf * 10240 + m * 80 + seg * 16;
            cpa16(sb + off,         g_FBh + (size_t)m * NL + l0 + seg * 8);
            cpa16(sb + 20480 + off, g_FBl + (size_t)m * NL + l0 + seg * 8);
        }
        cpa_commit();
    };
    float4 pB[4];
    auto loadB = [&](int l0) {
        const float* src = qb + (size_t)(l0 + lq) * 512 + iq;
        pB[0] = *(const float4*)src;       pB[1] = *(const float4*)(src + 4);
        pB[2] = *(const float4*)(src + 8); pB[3] = *(const float4*)(src + 12);
    };
    auto storeB = [&](int buf) {
        unsigned hw[8], lw[8];
#pragma unroll
        for (int j = 0; j < 4; j++) {
            hl2(pB[j].x, pB[j].y, hw[j * 2], lw[j * 2]);
            hl2(pB[j].z, pB[j].w, hw[j * 2 + 1], lw[j * 2 + 1]);
        }
        unsigned off = (unsigned)buf * 8704 + lq * 272 + iq * 2;
        *(uint4*)(sm + 40960 + off)      = make_uint4(hw[0], hw[1], hw[2], hw[3]);
        *(uint4*)(sm + 40960 + off + 16) = make_uint4(hw[4], hw[5], hw[6], hw[7]);
        *(uint4*)(sm + 58368 + off)      = make_uint4(lw[0], lw[1], lw[2], lw[3]);
        *(uint4*)(sm + 58368 + off + 16) = make_uint4(lw[4], lw[5], lw[6], lw[7]);
    };

    float c[2][8][4] = {};
    stageA_async(0, base);
    loadB(base);
    cpa_wait0();
    storeB(0);
    __syncthreads();
    for (int ch = 0; ch < 32; ch++) {
        int buf = ch & 1;
        if (ch + 1 < 32) { stageA_async(buf ^ 1, base + (ch + 1) * 32); loadB(base + (ch + 1) * 32); }
#pragma unroll
        for (int ks = 0; ks < 2; ks++) {
            unsigned ah[2][4], al[2][4];
#pragma unroll
            for (int mt = 0; mt < 2; mt++) {
                unsigned row = wm * 32 + mt * 16 + (lane & 7) + ((lane >> 3) & 1) * 8;
                unsigned col = ks * 16 + ((lane >> 4) & 1) * 8;
                unsigned off = (unsigned)buf * 10240 + row * 80 + col * 2;
                ldm_x4(sb + off, ah[mt]);
                ldm_x4(sb + 20480 + off, al[mt]);
            }
#pragma unroll
            for (int ntp = 0; ntp < 4; ntp++) {
                unsigned bhf[2][2], blf[2][2];
#pragma unroll
                for (int j = 0; j < 2; j++) {
                    int nt = ntp * 2 + j;
                    unsigned row = ks * 16 + (lane & 15);
                    unsigned off = (unsigned)buf * 8704 + row * 272 + (wn * 64 + nt * 8) * 2;
                    ldm_x2t(sb + 40960 + off, bhf[j]);
                    ldm_x2t(sb + 58368 + off, blf[j]);
                }
#pragma unroll
                for (int mt = 0; mt < 2; mt++)
#pragma unroll
                    for (int j = 0; j < 2; j++) {
                        int nt = ntp * 2 + j;
                        mma_bf16(c[mt][nt], ah[mt], bhf[j]);
                        mma_bf16(c[mt][nt], ah[mt], blf[j]);
                        mma_bf16(c[mt][nt], al[mt], bhf[j]);
                    }
            }
        }
        if (ch + 1 < 32) { cpa_wait0(); storeB(buf ^ 1); }
        __syncthreads();
    }
    int bh = b * 8 + hp * 2 + wn;                 // wn selects the head
    float* xf = g_XF + (size_t)p * XPART + (size_t)bh * 128 * 64;
#pragma unroll
    for (int mt = 0; mt < 2; mt++) {
        int m0 = wm * 32 + mt * 16 + (lane >> 2);
#pragma unroll
        for (int nt = 0; nt < 8; nt++) {
            int n = nt * 8 + 2 * (lane & 3);      // 0..63 within head
            *(float2*)&xf[(size_t)m0 * 64 + n]       = make_float2(c[mt][nt][0], c[mt][nt][1]);
            *(float2*)&xf[(size_t)(m0 + 8) * 64 + n] = make_float2(c[mt][nt][2], c[mt][nt][3]);
        }
    }
}

// ---------------- K2: complex mode mixing (sums 2 K-parts) ----------------
// dyn smem: Xr[64][36] @0 (9216), Xi @9216, Wr[64][64] @18432 (16384), Wi @34816. tot 51200.
__global__ __launch_bounds__(128) void k_mix() {
    extern __shared__ __align__(16) char sm[];
    float* Xr = (float*)sm;
    float* Xi = (float*)(sm + 9216);
    float* Wr = (float*)(sm + 18432);
    float* Wi = (float*)(sm + 34816);
    int h = blockIdx.x >> 6, m = blockIdx.x & 63, t = threadIdx.x;
#pragma unroll
    for (int p = 0; p < 16; p++) {
        int u = p * 128 + t;
        int b = u >> 6, i = u & 63;
        size_t base = ((size_t)(b * 8 + h) * 128 + m) * 64;
        Xr[i * 36 + b] = g_XF[base + i] + g_XF[XPART + base + i];
        Xi[i * 36 + b] = g_XF[base + 4096 + i] + g_XF[XPART + base + 4096 + i];
    }
#pragma unroll
    for (int p = 0; p < 32; p++) {
        int u = p * 128 + t, i = u >> 6, o = u & 63;
        size_t base = (size_t)((h * 64 + m) * 64 + i) * 64 + o;
        Wr[i * 64 + o] = g_WtR[base];
        Wi[i * 64 + o] = g_WtI[base];
    }
    __syncthreads();
    int og = (t & 15) * 4, bg = (t >> 4) * 4;
    float ar[4][4], ai[4][4];
#pragma unroll
    for (int j = 0; j < 4; j++)
#pragma unroll
        for (int cc = 0; cc < 4; cc++) { ar[j][cc] = 0.0f; ai[j][cc] = 0.0f; }
    for (int i = 0; i < 64; i++) {
        float4 wr = *(const float4*)&Wr[i * 64 + og];
        float4 wv = *(const float4*)&Wi[i * 64 + og];
        float4 xr = *(const float4*)&Xr[i * 36 + bg];
        float4 xv = *(const float4*)&Xi[i * 36 + bg];
        float wrv[4] = {wr.x, wr.y, wr.z, wr.w}, wvv[4] = {wv.x, wv.y, wv.z, wv.w};
        float xrv[4] = {xr.x, xr.y, xr.z, xr.w}, xvv[4] = {xv.x, xv.y, xv.z, xv.w};
#pragma unroll
        for (int j = 0; j < 4; j++)
#pragma unroll
            for (int cc = 0; cc < 4; cc++) {
                ar[j][cc] += xrv[j] * wrv[cc] - xvv[j] * wvv[cc];
                ai[j][cc] += xrv[j] * wvv[cc] + xvv[j] * wrv[cc];
            }
    }
#pragma unroll
    for (int j = 0; j < 4; j++) {
        int bh = (bg + j) * 8 + h;
        unsigned h0, l0, h1, l1;
        size_t w0 = ((size_t)bh * 128 + m) * 32 + og / 2;
        hl2(ar[j][0], ar[j][1], h0, l0); hl2(ar[j][2], ar[j][3], h1, l1);
        g_O2h[w0] = h0; g_O2h[w0 + 1] = h1; g_O2l[w0] = l0; g_O2l[w0 + 1] = l1;
        size_t w1 = ((size_t)bh * 128 + 64 + m) * 32 + og / 2;
        hl2(ai[j][0], ai[j][1], h0, l0); hl2(ai[j][2], ai[j][3], h1, l1);
        g_O2h[w1] = h0; g_O2h[w1 + 1] = h1; g_O2l[w1] = l0; g_O2l[w1 + 1] = l1;
    }
}

// ---------------- K3: inverse, mma.sync, reg-prefetch pipeline (unchanged from R13) ----------------
__global__ __launch_bounds__(256, 2) void k_inv(float* __restrict__ out) {
    extern __shared__ __align__(16) char sm[];
    unsigned sb = s2u(sm);
    int tid = threadIdx.x, lane = tid & 31, w = tid >> 5;
    int g = blockIdx.x & 63, lt = blockIdx.x >> 6;
    int wm = w & 1, wn = w >> 1;

#pragma unroll
    for (int rpt = 0; rpt < 8; rpt++) {
        int u = rpt * 256 + tid;
        int l = u >> 4, seg = u & 15;
        unsigned off = l * 272 + seg * 16;
        *(uint4*)(sm + off)         = *(const uint4*)(g_IBh + (size_t)(lt * 128 + l) * 128 + seg * 8);
        *(uint4*)(sm + 34816 + off) = *(const uint4*)(g_IBl + (size_t)(lt * 128 + l) * 128 + seg * 8);
    }

    uint4 pH[4], pL[4];
    auto loadO2 = [&](int bh) {
#pragma unroll
        for (int rpt = 0; rpt < 4; rpt++) {
            int u = rpt * 256 + tid;
            int k = u >> 3, seg = u & 7;
            pH[rpt] = *(const uint4*)(g_O2h + (size_t)bh * 4096 + k * 32 + seg * 4);
            pL[rpt] = *(const uint4*)(g_O2l + (size_t)bh * 4096 + k * 32 + seg * 4);
        }
    };
    loadO2(g * 4);

    for (int bj = 0; bj < 4; bj++) {
        int bh = g * 4 + bj;
        __syncthreads();
#pragma unroll
        for (int rpt = 0; rpt < 4; rpt++) {
            int u = rpt * 256 + tid;
            int k = u >> 3, seg = u & 7;
            unsigned off = k * 144 + seg * 16;
            *(uint4*)(sm + 69632 + off) = pH[rpt];
            *(uint4*)(sm + 88064 + off) = pL[rpt];
        }
        __syncthreads();
        if (bj < 3) loadO2(bh + 1);
        float c[2][4][4] = {};
#pragma unroll
        for (int ks = 0; ks < 8; ks++) {
            int k0 = ks * 16;
            unsigned ah[2][4], al[2][4];
#pragma unroll
            for (int mt = 0; mt < 2; mt++) {
                unsigned row = k0 + (lane & 7) + ((lane >> 4) & 1) * 8;
                unsigned col = wm * 32 + mt * 16 + ((lane >> 3) & 1) * 8;
                unsigned off = row * 144 + col * 2;
                ldm_x4t(sb + 69632 + off, ah[mt]);
                ldm_x4t(sb + 88064 + off, al[mt]);
            }
#pragma unroll
            for (int ntp = 0; ntp < 2; ntp++) {
                unsigned bhf[2][2], blf[2][2];
#pragma unroll
                for (int j = 0; j < 2; j++) {
                    int nt = ntp * 2 + j;
                    unsigned row = wn * 32 + nt * 8 + (lane & 7);
                    unsigned col = k0 + ((lane >> 3) & 1) * 8;
                    unsigned off = row * 272 + col * 2;
                    ldm_x2(sb + off, bhf[j]);
                    ldm_x2(sb + 34816 + off, blf[j]);
                }
#pragma unroll
                for (int mt = 0; mt < 2; mt++)
#pragma unroll
                    for (int j = 0; j < 2; j++) {
                        int nt = ntp * 2 + j;
                        mma_bf16(c[mt][nt], ah[mt], bhf[j]);
                        mma_bf16(c[mt][nt], ah[mt], blf[j]);
                        mma_bf16(c[mt][nt], al[mt], bhf[j]);
                    }
            }
        }
        float* yb = out + (size_t)bh * 64 * NL + lt * 128;
#pragma unroll
        for (int mt = 0; mt < 2; mt++) {
            int o = wm * 32 + mt * 16 + (lane >> 2);
#pragma unroll
            for (int nt = 0; nt < 4; nt++) {
                int l = wn * 32 + nt * 8 + 2 * (lane & 3);
                *(float2*)&yb[(size_t)o * NL + l]       = make_float2(c[mt][nt][0], c[mt][nt][1]);
                *(float2*)&yb[(size_t)(o + 8) * NL + l] = make_float2(c[mt][nt][2], c[mt][nt][3]);
            }
        }
    }
}

// ---------------- launch ----------------
extern "C" void kernel_launch(void* const* d_in, const int* in_sizes, int n_in,
                              void* d_out, int out_size) {
    const float* q     = (const float*)d_in[0];
    const float* wreal = (const float*)d_in[3];
    const float* wimag = (const float*)d_in[4];
    const int*   index = (const int*)d_in[5];
    float* out = (float*)d_out;

    cudaFuncSetAttribute(k_fwd, cudaFuncAttributeMaxDynamicSharedMemorySize, 75776);
    cudaFuncSetAttribute(k_mix, cudaFuncAttributeMaxDynamicSharedMemorySize, 51200);
    cudaFuncSetAttribute(k_inv, cudaFuncAttributeMaxDynamicSharedMemorySize, 106496);

    k_basisF<<<1024, 256>>>(index);               // launch 0
    k_wt<<<512, 256>>>(wreal, wimag);             // launch 1
    k_basisI<<<1024, 256>>>();                    // launch 2
    k_fwd<<<256, 256, 75776>>>(q);                // launch 3  <- profiled slot
    k_mix<<<512, 128, 51200>>>();                 // launch 4
    k_inv<<<1024, 256, 106496>>>(out);            // launch 5
}